// round 4
// baseline (speedup 1.0000x reference)
#include <cuda_runtime.h>
#include <cuda_bf16.h>
#include <cstdint>

// ---------------------------------------------------------------------------
// QuantizedLinear via legacy mma.sync IMMA (sm_103 base target — tcgen05 is
// 'a'-gated and this harness compiles PTX at compute_103).
//   q_in = clip(rint(x/s_in)+zp_in) ; acc = q_in·W^T + bias ;
//   out  = (float)clip(rint((float)acc/s_out)+zp_out)        [f32 out buffer]
// M=8192, K=4096, N=4096.
// GEMM: 128x128 CTA tile, BK=64B, cp.async 2-stage, 8 warps (2x4),
//       warp tile 64x32, mma.m16n8k32.s8.s8.s32.
// ---------------------------------------------------------------------------

#define MAX_M 8192
#define MAX_K 4096
#define MAX_N 8192

__device__ int8_t g_qin[(size_t)MAX_M * MAX_K];   // quantized input [M,K]
__device__ int8_t g_w[(size_t)MAX_N * MAX_K];     // repacked weight [N,K]
__device__ int    g_bias[MAX_N];
__device__ int    g_wtype;   // 0=i8, 1=i32, 2=f32
__device__ int    g_btype;   // 1=i32, 2=f32

// ---------------- helpers ---------------------------------------------------
__device__ __forceinline__ uint32_t smem_u32(const void* p) {
    uint32_t a;
    asm("{ .reg .u64 t; cvta.to.shared.u64 t, %1; cvt.u32.u64 %0, t; }"
        : "=r"(a) : "l"(p));
    return a;
}
__device__ __forceinline__ float read_scale_f(const void* p, float lo, float hi) {
    float f = *(const float*)p;
    if (isfinite(f) && f > lo && f < hi) return f;
    return (float)(*(const double*)p);
}
__device__ __forceinline__ int clamp_i8(int v) { return max(-128, min(127, v)); }

__device__ __forceinline__ void cp_async16(uint32_t dst, const void* src) {
    asm volatile("cp.async.cg.shared.global [%0], [%1], 16;"
                 :: "r"(dst), "l"(src) : "memory");
}
#define CP_COMMIT() asm volatile("cp.async.commit_group;" ::: "memory")

__device__ __forceinline__ void mma_s8(int* d, const int* a, const int* b) {
    asm volatile(
        "mma.sync.aligned.m16n8k32.row.col.s32.s8.s8.s32 "
        "{%0,%1,%2,%3}, {%4,%5,%6,%7}, {%8,%9}, {%0,%1,%2,%3};"
        : "+r"(d[0]), "+r"(d[1]), "+r"(d[2]), "+r"(d[3])
        : "r"(a[0]), "r"(a[1]), "r"(a[2]), "r"(a[3]),
          "r"(b[0]), "r"(b[1]));
}

// ---------------- dtype detect / repack ------------------------------------
__global__ void detect_kernel(const void* w, const void* b) {
    if (threadIdx.x != 0 || blockIdx.x != 0) return;
    {
        const int* wi = (const int*)w; const float* wf = (const float*)w;
        bool i32 = true, f32 = true;
        for (int i = 0; i < 16; i++) {
            if (wi[i] < -128 || wi[i] > 127) i32 = false;
            float f = wf[i];
            if (!isfinite(f) || f != rintf(f) || fabsf(f) > 128.0f) f32 = false;
        }
        g_wtype = i32 ? 1 : (f32 ? 2 : 0);
    }
    {
        const int* bi = (const int*)b; const float* bf = (const float*)b;
        bool i32 = true, f32 = true;
        for (int i = 0; i < 16; i++) {
            if (bi[i] < -32768 || bi[i] > 32767) i32 = false;
            float f = bf[i];
            if (!isfinite(f) || f != rintf(f) || fabsf(f) > 65536.0f) f32 = false;
        }
        g_btype = i32 ? 1 : 2;
    }
}

__global__ void convert_weight_kernel(const void* __restrict__ w, int n4) {
    int i = blockIdx.x * blockDim.x + threadIdx.x;
    if (i >= n4) return;
    int ty = g_wtype;
    char4 q;
    if (ty == 0) {
        q = ((const char4*)w)[i];
    } else if (ty == 1) {
        int4 v = ((const int4*)w)[i];
        q.x = (char)v.x; q.y = (char)v.y; q.z = (char)v.z; q.w = (char)v.w;
    } else {
        float4 v = ((const float4*)w)[i];
        q.x = (char)(int)rintf(v.x); q.y = (char)(int)rintf(v.y);
        q.z = (char)(int)rintf(v.z); q.w = (char)(int)rintf(v.w);
    }
    ((char4*)g_w)[i] = q;
}

__global__ void convert_bias_kernel(const void* __restrict__ b, int n) {
    int i = blockIdx.x * blockDim.x + threadIdx.x;
    if (i >= n) return;
    g_bias[i] = (g_btype == 2) ? (int)rintf(((const float*)b)[i])
                               : ((const int*)b)[i];
}

// ---------------- Stage 1: quantize input ----------------------------------
__global__ void quant_kernel(const float4* __restrict__ x,
                             const void* __restrict__ s_p,
                             const int* __restrict__ zp_p, int n4) {
    int i = blockIdx.x * blockDim.x + threadIdx.x;
    if (i >= n4) return;
    float s = read_scale_f(s_p, 1e-6f, 1e3f);
    int zp = __ldg(zp_p);
    float4 v = x[i];
    char4 q;
    q.x = (char)clamp_i8((int)rintf(v.x / s) + zp);
    q.y = (char)clamp_i8((int)rintf(v.y / s) + zp);
    q.z = (char)clamp_i8((int)rintf(v.z / s) + zp);
    q.w = (char)clamp_i8((int)rintf(v.w / s) + zp);
    ((char4*)g_qin)[i] = q;
}

// ---------------- Stage 2: IMMA GEMM ---------------------------------------
#define BM 128
#define BN 128
#define BKB 64          // K bytes per tile
#define LDS_PAD 80      // 64 data + 16 pad -> conflict-free fragment reads

__global__ __launch_bounds__(256, 2)
void gemm_imma_kernel(float* __restrict__ C, int M, int N, int K,
                      const void* __restrict__ os_p,
                      const int* __restrict__ ozp_p) {
    __shared__ int8_t sA[2][BM][LDS_PAD];
    __shared__ int8_t sB[2][BN][LDS_PAD];

    const int t   = threadIdx.x;
    const int wid = t >> 5;
    const int lid = t & 31;
    const int g   = lid >> 2;      // groupID 0..7
    const int t4  = lid & 3;       // thread in group
    const int wm  = wid >> 2;      // 0..1  (warp m)
    const int wn  = wid & 3;       // 0..3  (warp n)
    const int bm  = blockIdx.y * BM;
    const int bn  = blockIdx.x * BN;

    // global load mapping: 512 16B chunks per tile side, 2 per thread
    const int lrow0 = t >> 1;             // chunks 0..255: row = c>>1? no:
    // c = t + l*256 ; row = c >> 2 (0..127), seg = (c & 3)*16
    const int8_t* gA = g_qin + (size_t)bm * K;
    const int8_t* gB = g_w   + (size_t)bn * K;

    int acc[4][4][4];
#pragma unroll
    for (int i = 0; i < 4; i++)
#pragma unroll
        for (int j = 0; j < 4; j++)
#pragma unroll
            for (int r = 0; r < 4; r++) acc[i][j][r] = 0;

    const uint32_t sA_u = smem_u32(&sA[0][0][0]);
    const uint32_t sB_u = smem_u32(&sB[0][0][0]);
    const uint32_t stageBytes = BM * LDS_PAD;

    auto load_tiles = [&](int stage, int k0) {
#pragma unroll
        for (int l = 0; l < 2; l++) {
            int c   = t + l * 256;
            int row = c >> 2;
            int seg = (c & 3) * 16;
            uint32_t doff = stage * stageBytes + row * LDS_PAD + seg;
            cp_async16(sA_u + doff, gA + (size_t)row * K + k0 + seg);
            cp_async16(sB_u + doff, gB + (size_t)row * K + k0 + seg);
        }
        CP_COMMIT();
    };

    const int niter = K / BKB;
    load_tiles(0, 0);

    for (int it = 0; it < niter; it++) {
        if (it + 1 < niter) {
            load_tiles((it + 1) & 1, (it + 1) * BKB);
            asm volatile("cp.async.wait_group 1;" ::: "memory");
        } else {
            asm volatile("cp.async.wait_group 0;" ::: "memory");
        }
        __syncthreads();

        const int st = it & 1;
#pragma unroll
        for (int ks = 0; ks < 2; ks++) {
            const int kb = ks * 32;
            int afrag[4][4], bfrag[4][2];
#pragma unroll
            for (int mt = 0; mt < 4; mt++) {
                const int r0 = wm * 64 + mt * 16 + g;
                afrag[mt][0] = *(const int*)&sA[st][r0    ][kb + t4 * 4];
                afrag[mt][1] = *(const int*)&sA[st][r0 + 8][kb + t4 * 4];
                afrag[mt][2] = *(const int*)&sA[st][r0    ][kb + t4 * 4 + 16];
                afrag[mt][3] = *(const int*)&sA[st][r0 + 8][kb + t4 * 4 + 16];
            }
#pragma unroll
            for (int nt = 0; nt < 4; nt++) {
                const int br = wn * 32 + nt * 8 + g;
                bfrag[nt][0] = *(const int*)&sB[st][br][kb + t4 * 4];
                bfrag[nt][1] = *(const int*)&sB[st][br][kb + t4 * 4 + 16];
            }
#pragma unroll
            for (int mt = 0; mt < 4; mt++)
#pragma unroll
                for (int nt = 0; nt < 4; nt++)
                    mma_s8(acc[mt][nt], afrag[mt], bfrag[nt]);
        }
        __syncthreads();
    }

    // ---------------- epilogue ----------------------------------------------
    const float os = read_scale_f(os_p, 1e-3f, 1e9f);
    const int ozp = __ldg(ozp_p);

#pragma unroll
    for (int mt = 0; mt < 4; mt++) {
        const int row0 = bm + wm * 64 + mt * 16 + g;
#pragma unroll
        for (int nt = 0; nt < 4; nt++) {
            const int col0 = bn + wn * 32 + nt * 8 + t4 * 2;
            const int b0 = g_bias[col0];
            const int b1 = g_bias[col0 + 1];
            float2 lo, hi;
            lo.x = (float)clamp_i8((int)rintf((float)(acc[mt][nt][0] + b0) / os) + ozp);
            lo.y = (float)clamp_i8((int)rintf((float)(acc[mt][nt][1] + b1) / os) + ozp);
            hi.x = (float)clamp_i8((int)rintf((float)(acc[mt][nt][2] + b0) / os) + ozp);
            hi.y = (float)clamp_i8((int)rintf((float)(acc[mt][nt][3] + b1) / os) + ozp);
            *(float2*)&C[(size_t)row0 * N + col0]       = lo;
            *(float2*)&C[(size_t)(row0 + 8) * N + col0] = hi;
        }
    }
}

// ---------------------------------------------------------------------------
extern "C" void kernel_launch(void* const* d_in, const int* in_sizes, int n_in,
                              void* d_out, int out_size) {
    const float* input  = (const float*)d_in[0];
    const void*  weight = d_in[1];
    const void*  bias   = d_in[2];
    const void*  in_s   = d_in[3];
    const int*   in_zp  = (const int*)d_in[4];
    const void*  out_s  = d_in[5];
    const int*   out_zp = (const int*)d_in[6];

    const int N = in_sizes[2];
    const int K = in_sizes[1] / N;
    const int M = in_sizes[0] / K;

    float* out = (float*)d_out;

    detect_kernel<<<1, 32>>>(weight, bias);

    int wn4 = (N * K) / 4;
    convert_weight_kernel<<<(wn4 + 255) / 256, 256>>>(weight, wn4);
    convert_bias_kernel<<<(N + 255) / 256, 256>>>(bias, N);

    int n4 = (M * K) / 4;
    quant_kernel<<<(n4 + 255) / 256, 256>>>((const float4*)input, in_s, in_zp, n4);

    dim3 grid(N / BN, M / BM);
    gemm_imma_kernel<<<grid, 256>>>(out, M, N, K, out_s, out_zp);
}